// round 14
// baseline (speedup 1.0000x reference)
#include <cuda_runtime.h>
#include <cuda_bf16.h>
#include <cstdint>

// Problem constants
#define B_   2
#define S_   2048
#define D_   1024
#define H_   16
#define HD_  64
#define E_   8
#define F_   1024
#define T_   (B_ * S_)            // 4096 tokens
#define PMAX_ (T_ * 2 + E_ * 128) // 9216 padded token-expert pairs

// ---------------------------------------------------------------------------
// Scratch (static device globals) — fp32 (tf32-exact where GEMM-consumed)
// ---------------------------------------------------------------------------
__device__ float g_xn[T_ * D_];      // rmsnorm(x), tf32-rounded
__device__ float g_q[T_ * D_];
__device__ float g_k[T_ * D_];
__device__ float g_v[T_ * D_];
__device__ float g_attn[T_ * D_];    // tf32-rounded (GEMM A operand)
__device__ float g_h[T_ * D_];
__device__ float g_hn[T_ * D_];      // full fp32 (router)
__device__ float g_hnr[T_ * D_];     // tf32-rounded (MoE GEMM A operand)
__device__ float g_t1[PMAX_ * F_];   // x @ w1 (full fp32, silu input)
__device__ float g_a[PMAX_ * F_];    // silu(t1)*(x@w3), tf32-rounded
__device__ float g_h2[PMAX_ * D_];   // a @ w2

// tf32-rounded fp32 transposed weights [N][K]
__device__ float g_wqT[D_ * D_];
__device__ float g_wkT[D_ * D_];
__device__ float g_wvT[D_ * D_];
__device__ float g_woT[D_ * D_];
__device__ float g_w1T[E_ * D_ * F_];
__device__ float g_w3T[E_ * D_ * F_];
__device__ float g_w2T[E_ * F_ * D_];

__device__ int   g_topk_idx[T_ * 2];
__device__ float g_topk_gate[T_ * 2];
__device__ int   g_tok_pos[T_ * 2];
__device__ int   g_pair_tok[PMAX_];
__device__ int   g_cnt[E_];
__device__ int   g_cur[E_];
__device__ int   g_off[E_ + 1];

// ---------------------------------------------------------------------------
// Helpers
// ---------------------------------------------------------------------------
__device__ __forceinline__ uint32_t f2tf32(float f) {
    uint32_t u;
    asm("cvt.rna.tf32.f32 %0, %1;" : "=r"(u) : "f"(f));
    return u;
}
__device__ __forceinline__ float rtf(float f) {   // rna round to tf32, as float
    return __uint_as_float(f2tf32(f));
}

__device__ __forceinline__ void mma_tf32(
    float& c0, float& c1, float& c2, float& c3,
    uint32_t a0, uint32_t a1, uint32_t a2, uint32_t a3,
    uint32_t b0, uint32_t b1)
{
    asm volatile(
        "mma.sync.aligned.m16n8k8.row.col.f32.tf32.tf32.f32 "
        "{%0,%1,%2,%3}, {%4,%5,%6,%7}, {%8,%9}, {%0,%1,%2,%3};"
        : "+f"(c0), "+f"(c1), "+f"(c2), "+f"(c3)
        : "r"(a0), "r"(a1), "r"(a2), "r"(a3), "r"(b0), "r"(b1));
}

__device__ __forceinline__ float silu_f(float u) {
    return u * (1.f / (1.f + __expf(-u)));
}

__device__ __forceinline__ void cp16(uint32_t dst, const void* src) {
    asm volatile("cp.async.cg.shared.global [%0], [%1], 16;" :: "r"(dst), "l"(src));
}
__device__ __forceinline__ void cp16z(uint32_t dst, const void* src, bool v) {
    int sz = v ? 16 : 0;
    asm volatile("cp.async.cg.shared.global [%0], [%1], 16, %2;"
                 :: "r"(dst), "l"(src), "r"(sz));
}

// ---------------------------------------------------------------------------
// Weight transpose + tf32 rounding: dst[n*1024+k] = tf32_rna(src[k*1024+n]).
// ---------------------------------------------------------------------------
template <int WHICH>
__global__ void __launch_bounds__(256) transpose_tf32_kernel(
    const float* __restrict__ src)
{
    float* dst =
        (WHICH == 0) ? g_wqT : (WHICH == 1) ? g_wkT : (WHICH == 2) ? g_wvT :
        (WHICH == 3) ? g_woT : (WHICH == 4) ? g_w1T : (WHICH == 5) ? g_w3T :
        g_w2T;
    __shared__ float t[32][33];
    size_t off = (size_t)blockIdx.z * 1024 * 1024;
    src += off; dst += off;
    int x = blockIdx.x * 32, y = blockIdx.y * 32;
    int tx = threadIdx.x & 31, ty = threadIdx.x >> 5;
    #pragma unroll
    for (int i = 0; i < 32; i += 8)
        t[ty + i][tx] = src[(size_t)(y + ty + i) * 1024 + x + tx];
    __syncthreads();
    #pragma unroll
    for (int i = 0; i < 32; i += 8)
        dst[(size_t)(x + ty + i) * 1024 + y + tx] = rtf(t[tx][ty + i]);
}

// ---------------------------------------------------------------------------
// RMSNorm. FROM_H=false: x -> g_xn (tf32-rounded).
//          FROM_H=true:  g_h -> g_hn (full) + g_hnr (tf32-rounded).
// ---------------------------------------------------------------------------
template <bool FROM_H>
__global__ void __launch_bounds__(256) rmsnorm_kernel(
    const float* __restrict__ xin, const float* __restrict__ w)
{
    int t   = blockIdx.x;
    int tid = threadIdx.x;
    const float* src = FROM_H ? g_h : xin;
    const float4* xr = reinterpret_cast<const float4*>(src + (size_t)t * D_);
    float4 v = xr[tid];
    float ss = v.x * v.x + v.y * v.y + v.z * v.z + v.w * v.w;
    #pragma unroll
    for (int o = 16; o > 0; o >>= 1) ss += __shfl_xor_sync(0xffffffffu, ss, o);
    __shared__ float red[8];
    __shared__ float s_inv;
    int warp = tid >> 5, lane = tid & 31;
    if (lane == 0) red[warp] = ss;
    __syncthreads();
    if (tid == 0) {
        float tot = 0.f;
        #pragma unroll
        for (int i = 0; i < 8; i++) tot += red[i];
        s_inv = rsqrtf(tot * (1.0f / (float)D_) + 1e-6f);
    }
    __syncthreads();
    float inv = s_inv;
    const float4* wr = reinterpret_cast<const float4*>(w);
    float4 wv = wr[tid];
    float4 o;
    o.x = v.x * inv * wv.x;
    o.y = v.y * inv * wv.y;
    o.z = v.z * inv * wv.z;
    o.w = v.w * inv * wv.w;
    size_t idx = (size_t)t * D_ + tid * 4;
    float4 orn = make_float4(rtf(o.x), rtf(o.y), rtf(o.z), rtf(o.w));
    if (FROM_H) {
        *reinterpret_cast<float4*>(&g_hn[idx])  = o;    // full fp32 for router
        *reinterpret_cast<float4*>(&g_hnr[idx]) = orn;  // tf32-exact for GEMM
    } else {
        *reinterpret_cast<float4*>(&g_xn[idx])  = orn;
    }
}

// ---------------------------------------------------------------------------
// tf32 tensor-core GEMM, cp.async double-buffered, NO cvt in mainloop
// (all operands pre-rounded rna => HW truncation is a no-op).
// 128x128 tile, k-slab 16, 2 stages, 256 threads, warp = 64x32 (4x4 m16n8k8).
// MODE 0: g_xn @ {wq,wk,wv}T[z] -> g_q/g_k/g_v
// MODE 3: g_attn @ woT + R -> g_h
// MODE 4: gather(g_hnr) @ w1T[e] -> g_t1
// MODE 5: gather(g_hnr) @ w3T[e], epilogue silu(g_t1)*acc -> g_a (rounded)
// MODE 6: g_a @ w2T[e] -> g_h2
// ---------------------------------------------------------------------------
template <int MODE>
__global__ void __launch_bounds__(256) tf32_gemm_kernel(const float* __restrict__ R)
{
    constexpr int K   = 1024;
    constexpr int AST = 20;            // smem stride (floats), conflict-free
    int m0 = blockIdx.y * 128;
    if (MODE >= 4 && m0 >= g_off[E_]) return;

    const float* Bt;
    if (MODE == 0) {
        int z = blockIdx.z;
        Bt = (z == 0) ? g_wqT : (z == 1) ? g_wkT : g_wvT;
    } else if (MODE == 3) {
        Bt = g_woT;
    } else {
        int e = 0;
        while (m0 >= g_off[e + 1]) e++;
        const float* base = (MODE == 4) ? g_w1T : (MODE == 5) ? g_w3T : g_w2T;
        Bt = base + (size_t)e * K * K;
    }

    int n0 = blockIdx.x * 128;
    int tid = threadIdx.x;
    int lrow = tid >> 2;          // 0..63
    int lc4  = (tid & 3) * 4;     // k offset 0,4,8,12 (floats; 16B each)

    const float* Arow[2];
    bool av[2];
    #pragma unroll
    for (int i = 0; i < 2; i++) {
        int r = m0 + lrow + 64 * i;
        if (MODE == 4 || MODE == 5) {
            int tok = g_pair_tok[r];
            av[i] = (tok >= 0);
            Arow[i] = g_hnr + (size_t)(tok < 0 ? 0 : tok) * K + lc4;
        } else {
            av[i] = true;
            const float* A = (MODE == 3) ? g_attn : (MODE == 6) ? g_a : g_xn;
            Arow[i] = A + (size_t)r * K + lc4;
        }
    }
    const float* Brow[2];
    #pragma unroll
    for (int i = 0; i < 2; i++)
        Brow[i] = Bt + (size_t)(n0 + lrow + 64 * i) * K + lc4;

    __shared__ __align__(16) float As[2][128 * AST];
    __shared__ __align__(16) float Bs[2][128 * AST];
    uint32_t aB = (uint32_t)__cvta_generic_to_shared(&As[0][0]);
    uint32_t bB = (uint32_t)__cvta_generic_to_shared(&Bs[0][0]);
    uint32_t aD[2], bD[2];
    #pragma unroll
    for (int i = 0; i < 2; i++) {
        aD[i] = aB + ((lrow + 64 * i) * AST + lc4) * 4;
        bD[i] = bB + ((lrow + 64 * i) * AST + lc4) * 4;
    }
    constexpr uint32_t STG_BYTES = 128 * AST * 4;  // 10240

    int lane = tid & 31;
    int wid  = tid >> 5;
    int wr   = wid & 1;
    int wc   = wid >> 1;
    int frow = lane >> 2;
    int kq   = lane & 3;

    float acc[4][4][4] = {};

    // prologue: stage 0 (kb = 0)
    cp16z(aD[0], Arow[0], av[0]);
    cp16z(aD[1], Arow[1], av[1]);
    cp16(bD[0], Brow[0]);
    cp16(bD[1], Brow[1]);
    asm volatile("cp.async.commit_group;");

    constexpr int NIT = K / 16;   // 64
    for (int it = 0; it < NIT; it++) {
        if (it + 1 < NIT) {
            uint32_t so = ((it + 1) & 1) * STG_BYTES;
            int kb = (it + 1) * 16;
            cp16z(aD[0] + so, Arow[0] + kb, av[0]);
            cp16z(aD[1] + so, Arow[1] + kb, av[1]);
            cp16(bD[0] + so, Brow[0] + kb);
            cp16(bD[1] + so, Brow[1] + kb);
            asm volatile("cp.async.commit_group;");
            asm volatile("cp.async.wait_group 1;");
        } else {
            asm volatile("cp.async.wait_group 0;");
        }
        __syncthreads();

        const uint32_t* Ash = reinterpret_cast<const uint32_t*>(&As[it & 1][0]);
        const uint32_t* Bsh = reinterpret_cast<const uint32_t*>(&Bs[it & 1][0]);
        #pragma unroll
        for (int ks = 0; ks < 16; ks += 8) {
            uint32_t af[4][4];
            #pragma unroll
            for (int mt = 0; mt < 4; mt++) {
                int m = wr * 64 + mt * 16 + frow;
                af[mt][0] = Ash[m * AST + ks + kq];
                af[mt][1] = Ash[(m + 8) * AST + ks + kq];
                af[mt][2] = Ash[m * AST + ks + kq + 4];
                af[mt][3] = Ash[(m + 8) * AST + ks + kq + 4];
            }
            uint32_t bf[4][2];
            #pragma unroll
            for (int nt = 0; nt < 4; nt++) {
                int n = wc * 32 + nt * 8 + frow;
                bf[nt][0] = Bsh[n * AST + ks + kq];
                bf[nt][1] = Bsh[n * AST + ks + kq + 4];
            }
            #pragma unroll
            for (int mt = 0; mt < 4; mt++)
                #pragma unroll
                for (int nt = 0; nt < 4; nt++)
                    mma_tf32(acc[mt][nt][0], acc[mt][nt][1],
                             acc[mt][nt][2], acc[mt][nt][3],
                             af[mt][0], af[mt][1], af[mt][2], af[mt][3],
                             bf[nt][0], bf[nt][1]);
        }
        __syncthreads();
    }

    #pragma unroll
    for (int mt = 0; mt < 4; mt++) {
        int r = m0 + wr * 64 + mt * 16 + frow;
        #pragma unroll
        for (int nt = 0; nt < 4; nt++) {
            int c = n0 + wc * 32 + nt * 8 + kq * 2;
            size_t i0 = (size_t)r * K + c;
            size_t i1 = (size_t)(r + 8) * K + c;
            float2 v0 = make_float2(acc[mt][nt][0], acc[mt][nt][1]);
            float2 v1 = make_float2(acc[mt][nt][2], acc[mt][nt][3]);
            if (MODE == 3) {
                float2 r0 = *(const float2*)(R + i0);
                float2 r1 = *(const float2*)(R + i1);
                v0.x += r0.x; v0.y += r0.y;
                v1.x += r1.x; v1.y += r1.y;
            }
            if (MODE == 5) {
                float2 t10 = *(const float2*)(g_t1 + i0);
                float2 t11 = *(const float2*)(g_t1 + i1);
                v0.x = rtf(v0.x * silu_f(t10.x));
                v0.y = rtf(v0.y * silu_f(t10.y));
                v1.x = rtf(v1.x * silu_f(t11.x));
                v1.y = rtf(v1.y * silu_f(t11.y));
            }
            float* C;
            if (MODE == 0) {
                int z = blockIdx.z;
                C = (z == 0) ? g_q : (z == 1) ? g_k : g_v;
            } else {
                C = (MODE == 3) ? g_h : (MODE == 4) ? g_t1 :
                    (MODE == 5) ? g_a : g_h2;
            }
            *(float2*)(C + i0) = v0;
            *(float2*)(C + i1) = v1;
        }
    }
}

// ---------------------------------------------------------------------------
// Tensor-core flash attention (tf32), causal. Epilogue writes tf32-rounded
// g_attn (GEMM A operand for wo projection).
// ---------------------------------------------------------------------------
__global__ void __launch_bounds__(128) flash_mma_kernel()
{
    __shared__ uint32_t KVs[64 * 68];
    __shared__ uint32_t Ps[64 * 68];

    int qt = (int)gridDim.x - 1 - (int)blockIdx.x;  // long blocks first
    int h = blockIdx.y, b = blockIdx.z;
    int q0 = qt * 64;
    int tid = threadIdx.x;
    int w = tid >> 5, lane = tid & 31;
    int frow = lane >> 2, kq = lane & 3;
    int qw = w * 16;
    size_t base = ((size_t)b * S_) * D_ + (size_t)h * HD_;
    const float NI = -3.0e38f;

    uint32_t qf[8][4];
    {
        const float* Q0 = g_q + base + (size_t)(q0 + qw + frow) * D_;
        const float* Q1 = g_q + base + (size_t)(q0 + qw + frow + 8) * D_;
        #pragma unroll
        for (int ks = 0; ks < 8; ks++) {
            qf[ks][0] = f2tf32(0.125f * Q0[ks * 8 + kq]);
            qf[ks][1] = f2tf32(0.125f * Q1[ks * 8 + kq]);
            qf[ks][2] = f2tf32(0.125f * Q0[ks * 8 + kq + 4]);
            qf[ks][3] = f2tf32(0.125f * Q1[ks * 8 + kq + 4]);
        }
    }

    float oacc[8][4] = {};
    float m0 = NI, m1 = NI, l0 = 0.f, l1 = 0.f;

    for (int kt = 0; kt <= qt; kt++) {
        int k0 = kt * 64;
        __syncthreads();
        for (int i = tid; i < 1024; i += 128) {
            int r = i >> 4, c4 = (i & 15) * 4;
            float4 v = *(const float4*)&g_k[base + (size_t)(k0 + r) * D_ + c4];
            KVs[r * 68 + c4 + 0] = f2tf32(v.x);
            KVs[r * 68 + c4 + 1] = f2tf32(v.y);
            KVs[r * 68 + c4 + 2] = f2tf32(v.z);
            KVs[r * 68 + c4 + 3] = f2tf32(v.w);
        }
        __syncthreads();

        float sacc[8][4] = {};
        #pragma unroll
        for (int ks = 0; ks < 8; ks++) {
            uint32_t bf[8][2];
            #pragma unroll
            for (int nt = 0; nt < 8; nt++) {
                bf[nt][0] = KVs[(nt * 8 + frow) * 68 + ks * 8 + kq];
                bf[nt][1] = KVs[(nt * 8 + frow) * 68 + ks * 8 + kq + 4];
            }
            #pragma unroll
            for (int nt = 0; nt < 8; nt++)
                mma_tf32(sacc[nt][0], sacc[nt][1], sacc[nt][2], sacc[nt][3],
                         qf[ks][0], qf[ks][1], qf[ks][2], qf[ks][3],
                         bf[nt][0], bf[nt][1]);
        }

        if (kt == qt) {
            int r0g = qw + frow;
            #pragma unroll
            for (int nt = 0; nt < 8; nt++) {
                int c0g = nt * 8 + 2 * kq;
                if (c0g     > r0g)     sacc[nt][0] = NI;
                if (c0g + 1 > r0g)     sacc[nt][1] = NI;
                if (c0g     > r0g + 8) sacc[nt][2] = NI;
                if (c0g + 1 > r0g + 8) sacc[nt][3] = NI;
            }
        }

        float tm0 = NI, tm1 = NI;
        #pragma unroll
        for (int nt = 0; nt < 8; nt++) {
            tm0 = fmaxf(tm0, fmaxf(sacc[nt][0], sacc[nt][1]));
            tm1 = fmaxf(tm1, fmaxf(sacc[nt][2], sacc[nt][3]));
        }
        tm0 = fmaxf(tm0, __shfl_xor_sync(0xffffffffu, tm0, 1));
        tm0 = fmaxf(tm0, __shfl_xor_sync(0xffffffffu, tm0, 2));
        tm1 = fmaxf(tm1, __shfl_xor_sync(0xffffffffu, tm1, 1));
        tm1 = fmaxf(tm1, __shfl_xor_sync(0xffffffffu, tm1, 2));
        float mn0 = fmaxf(m0, tm0), mn1 = fmaxf(m1, tm1);
        float rs0 = 0.f, rs1 = 0.f;
        uint32_t* Pw = &Ps[(qw + frow) * 68];
        uint32_t* Pw8 = &Ps[(qw + frow + 8) * 68];
        #pragma unroll
        for (int nt = 0; nt < 8; nt++) {
            float p00 = __expf(sacc[nt][0] - mn0);
            float p01 = __expf(sacc[nt][1] - mn0);
            float p10 = __expf(sacc[nt][2] - mn1);
            float p11 = __expf(sacc[nt][3] - mn1);
            rs0 += p00 + p01;
            rs1 += p10 + p11;
            int c = nt * 8 + 2 * kq;
            Pw[c]      = f2tf32(p00);
            Pw[c + 1]  = f2tf32(p01);
            Pw8[c]     = f2tf32(p10);
            Pw8[c + 1] = f2tf32(p11);
        }
        rs0 += __shfl_xor_sync(0xffffffffu, rs0, 1);
        rs0 += __shfl_xor_sync(0xffffffffu, rs0, 2);
        rs1 += __shfl_xor_sync(0xffffffffu, rs1, 1);
        rs1 += __shfl_xor_sync(0xffffffffu, rs1, 2);
        float al0 = __expf(m0 - mn0), al1 = __expf(m1 - mn1);
        l0 = l0 * al0 + rs0;
        l1 = l1 * al1 + rs1;
        m0 = mn0; m1 = mn1;
        #pragma unroll
        for (int nt = 0; nt < 8; nt++) {
            oacc[nt][0] *= al0; oacc[nt][1] *= al0;
            oacc[nt][2] *= al1; oacc[nt][3] *= al1;
        }
        __syncwarp();
        __syncthreads();

        for (int i = tid; i < 1024; i += 128) {
            int r = i >> 4, c4 = (i & 15) * 4;
            float4 v = *(const float4*)&g_v[base + (size_t)(k0 + r) * D_ + c4];
            KVs[r * 68 + c4 + 0] = f2tf32(v.x);
            KVs[r * 68 + c4 + 1] = f2tf32(v.y);
            KVs[r * 68 + c4 + 2] = f2tf32(v.z);
            KVs[r * 68 + c4 + 3] = f2tf32(v.w);
        }
        __syncthreads();

        #pragma unroll
        for (int ks = 0; ks < 8; ks++) {
            uint32_t af[4];
            af[0] = Ps[(qw + frow) * 68 + ks * 8 + kq];
            af[1] = Ps[(qw + frow + 8) * 68 + ks * 8 + kq];
            af[2] = Ps[(qw + frow) * 68 + ks * 8 + kq + 4];
            af[3] = Ps[(qw + frow + 8) * 68 + ks * 8 + kq + 4];
            #pragma unroll
            for (int nt = 0; nt < 8; nt++) {
                uint32_t b0 = KVs[(ks * 8 + kq) * 68 + nt * 8 + frow];
                uint32_t b1 = KVs[(ks * 8 + kq + 4) * 68 + nt * 8 + frow];
                mma_tf32(oacc[nt][0], oacc[nt][1], oacc[nt][2], oacc[nt][3],
                         af[0], af[1], af[2], af[3], b0, b1);
            }
        }
    }

    float inv0 = 1.f / l0, inv1 = 1.f / l1;
    float* O0 = g_attn + base + (size_t)(q0 + qw + frow) * D_;
    float* O1 = g_attn + base + (size_t)(q0 + qw + frow + 8) * D_;
    #pragma unroll
    for (int nt = 0; nt < 8; nt++) {
        int c = nt * 8 + 2 * kq;
        *(float2*)(O0 + c) = make_float2(rtf(oacc[nt][0] * inv0),
                                         rtf(oacc[nt][1] * inv0));
        *(float2*)(O1 + c) = make_float2(rtf(oacc[nt][2] * inv1),
                                         rtf(oacc[nt][3] * inv1));
    }
}

// ---------------------------------------------------------------------------
// Router / dispatch (full-fp32 g_hn)
// ---------------------------------------------------------------------------
__global__ void __launch_bounds__(256) router_kernel(const float* __restrict__ rw)
{
    int t = (blockIdx.x * blockDim.x + threadIdx.x) >> 5;
    int lane = threadIdx.x & 31;
    if (t >= T_) return;
    float acc[8] = {0, 0, 0, 0, 0, 0, 0, 0};
    const float* xr = g_hn + (size_t)t * D_;
    for (int d = lane * 4; d < D_; d += 128) {
        float4 xv = *reinterpret_cast<const float4*>(xr + d);
        float xs[4] = {xv.x, xv.y, xv.z, xv.w};
        #pragma unroll
        for (int c = 0; c < 4; c++) {
            const float4* rp = reinterpret_cast<const float4*>(rw + (size_t)(d + c) * E_);
            float4 ra = rp[0], rb = rp[1];
            acc[0] += xs[c] * ra.x; acc[1] += xs[c] * ra.y;
            acc[2] += xs[c] * ra.z; acc[3] += xs[c] * ra.w;
            acc[4] += xs[c] * rb.x; acc[5] += xs[c] * rb.y;
            acc[6] += xs[c] * rb.z; acc[7] += xs[c] * rb.w;
        }
    }
    #pragma unroll
    for (int e = 0; e < 8; e++)
        #pragma unroll
        for (int o = 16; o > 0; o >>= 1)
            acc[e] += __shfl_xor_sync(0xffffffffu, acc[e], o);
    if (lane == 0) {
        int e0 = 0; float b0 = acc[0];
        #pragma unroll
        for (int e = 1; e < 8; e++) if (acc[e] > b0) { b0 = acc[e]; e0 = e; }
        int e1 = -1; float b1 = -3.4e38f;
        #pragma unroll
        for (int e = 0; e < 8; e++)
            if (e != e0 && acc[e] > b1) { b1 = acc[e]; e1 = e; }
        float ex = __expf(b1 - b0);
        float inv = 1.0f / (1.0f + ex);
        g_topk_idx[t * 2 + 0] = e0;
        g_topk_idx[t * 2 + 1] = e1;
        g_topk_gate[t * 2 + 0] = inv;
        g_topk_gate[t * 2 + 1] = ex * inv;
        atomicAdd(&g_cnt[e0], 1);
        atomicAdd(&g_cnt[e1], 1);
    }
}

__global__ void init_kernel()
{
    int i = blockIdx.x * blockDim.x + threadIdx.x;
    if (i < PMAX_) g_pair_tok[i] = -1;
    if (i < E_) g_cnt[i] = 0;
}

__global__ void offsets_kernel()
{
    int off = 0;
    for (int e = 0; e < E_; e++) {
        g_off[e] = off;
        off += (g_cnt[e] + 127) & ~127;
        g_cur[e] = 0;
    }
    g_off[E_] = off;
}

__global__ void __launch_bounds__(256) scatter_kernel()
{
    int t = blockIdx.x * blockDim.x + threadIdx.x;
    if (t >= T_) return;
    #pragma unroll
    for (int k = 0; k < 2; k++) {
        int e = g_topk_idx[t * 2 + k];
        int pos = g_off[e] + atomicAdd(&g_cur[e], 1);
        g_pair_tok[pos] = t;
        g_tok_pos[t * 2 + k] = pos;
    }
}

// ---------------------------------------------------------------------------
// Combine
// ---------------------------------------------------------------------------
__global__ void __launch_bounds__(256) combine_kernel(float* __restrict__ out)
{
    int i = blockIdx.x * blockDim.x + threadIdx.x;
    int t = i >> 8;
    int d = (i & 255) * 4;
    int p0 = g_tok_pos[t * 2 + 0], p1 = g_tok_pos[t * 2 + 1];
    float g0 = g_topk_gate[t * 2 + 0], g1 = g_topk_gate[t * 2 + 1];
    float4 hv = *reinterpret_cast<const float4*>(&g_h[(size_t)t * D_ + d]);
    float4 a = *reinterpret_cast<const float4*>(&g_h2[(size_t)p0 * D_ + d]);
    float4 b = *reinterpret_cast<const float4*>(&g_h2[(size_t)p1 * D_ + d]);
    float4 o;
    o.x = hv.x + g0 * a.x + g1 * b.x;
    o.y = hv.y + g0 * a.y + g1 * b.y;
    o.z = hv.z + g0 * a.z + g1 * b.z;
    o.w = hv.w + g0 * a.w + g1 * b.w;
    *reinterpret_cast<float4*>(&out[(size_t)i * 4]) = o;
}

// ---------------------------------------------------------------------------
// Launch: kernel launches ONLY
// ---------------------------------------------------------------------------
extern "C" void kernel_launch(void* const* d_in, const int* in_sizes, int n_in,
                              void* d_out, int out_size)
{
    const float* x   = (const float*)d_in[0];
    const float* anw = (const float*)d_in[1];
    const float* wq  = (const float*)d_in[2];
    const float* wk  = (const float*)d_in[3];
    const float* wv  = (const float*)d_in[4];
    const float* wo  = (const float*)d_in[5];
    const float* fnw = (const float*)d_in[6];
    const float* rw  = (const float*)d_in[7];
    const float* w1  = (const float*)d_in[8];
    const float* w3  = (const float*)d_in[9];
    const float* w2  = (const float*)d_in[10];
    float* out = (float*)d_out;

    dim3 gt1(32, 32, 1), gt8(32, 32, 8);
    transpose_tf32_kernel<0><<<gt1, 256>>>(wq);
    transpose_tf32_kernel<1><<<gt1, 256>>>(wk);
    transpose_tf32_kernel<2><<<gt1, 256>>>(wv);
    transpose_tf32_kernel<3><<<gt1, 256>>>(wo);
    transpose_tf32_kernel<4><<<gt8, 256>>>(w1);
    transpose_tf32_kernel<5><<<gt8, 256>>>(w3);
    transpose_tf32_kernel<6><<<gt8, 256>>>(w2);

    dim3 gqkv(8, 32, 3);
    dim3 gproj(8, 32);
    dim3 gmoe(8, PMAX_ / 128);

    rmsnorm_kernel<false><<<T_, 256>>>(x, anw);
    tf32_gemm_kernel<0><<<gqkv, 256>>>(nullptr);
    flash_mma_kernel<<<dim3(S_ / 64, H_, B_), 128>>>();
    tf32_gemm_kernel<3><<<gproj, 256>>>(x);
    rmsnorm_kernel<true><<<T_, 256>>>(nullptr, fnw);

    init_kernel<<<(PMAX_ + 255) / 256, 256>>>();
    router_kernel<<<T_ / 8, 256>>>(rw);
    offsets_kernel<<<1, 1>>>();
    scatter_kernel<<<T_ / 256, 256>>>();
    tf32_gemm_kernel<4><<<gmoe, 256>>>(nullptr);
    tf32_gemm_kernel<5><<<gmoe, 256>>>(nullptr);
    tf32_gemm_kernel<6><<<gmoe, 256>>>(nullptr);
    combine_kernel<<<(T_ * D_ / 4) / 256, 256>>>(out);
}

// round 16
// speedup vs baseline: 1.6072x; 1.6072x over previous
#include <cuda_runtime.h>
#include <cuda_bf16.h>
#include <cstdint>

// Problem constants
#define B_   2
#define S_   2048
#define D_   1024
#define H_   16
#define HD_  64
#define E_   8
#define F_   1024
#define T_   (B_ * S_)            // 4096 tokens
#define PMAX_ (T_ * 2 + E_ * 128) // 9216 padded token-expert pairs

// ---------------------------------------------------------------------------
// Scratch (static device globals)
// ---------------------------------------------------------------------------
__device__ float g_xn[T_ * D_];      // rmsnorm(x), tf32-rounded
__device__ float g_q[T_ * D_];
__device__ float g_k[T_ * D_];
__device__ float g_v[T_ * D_];
__device__ float g_attn[T_ * D_];    // tf32-rounded
__device__ float g_h[T_ * D_];
__device__ float g_hn[T_ * D_];      // full fp32 (router)
__device__ float g_hnr[T_ * D_];     // tf32-rounded (MoE GEMM A)
__device__ float g_t1[PMAX_ * F_];   // x @ w1 (full fp32)
__device__ float g_a[PMAX_ * F_];    // silu(t1)*(x@w3), tf32-rounded
__device__ float g_h2[PMAX_ * D_];   // a @ w2

// tf32-rounded weights, ORIGINAL [K][N] layout (no transpose)
__device__ float g_wq_r[D_ * D_];
__device__ float g_wk_r[D_ * D_];
__device__ float g_wv_r[D_ * D_];
__device__ float g_wo_r[D_ * D_];
__device__ float g_w1_r[E_ * D_ * F_];
__device__ float g_w3_r[E_ * D_ * F_];
__device__ float g_w2_r[E_ * F_ * D_];

__device__ int   g_topk_idx[T_ * 2];
__device__ float g_topk_gate[T_ * 2];
__device__ int   g_tok_pos[T_ * 2];
__device__ int   g_pair_tok[PMAX_];
__device__ int   g_cnt[E_];
__device__ int   g_cur[E_];
__device__ int   g_off[E_ + 1];

// ---------------------------------------------------------------------------
// Helpers
// ---------------------------------------------------------------------------
__device__ __forceinline__ uint32_t f2tf32(float f) {
    uint32_t u;
    asm("cvt.rna.tf32.f32 %0, %1;" : "=r"(u) : "f"(f));
    return u;
}
__device__ __forceinline__ float rtf(float f) {
    return __uint_as_float(f2tf32(f));
}

__device__ __forceinline__ void mma_tf32(
    float& c0, float& c1, float& c2, float& c3,
    uint32_t a0, uint32_t a1, uint32_t a2, uint32_t a3,
    uint32_t b0, uint32_t b1)
{
    asm volatile(
        "mma.sync.aligned.m16n8k8.row.col.f32.tf32.tf32.f32 "
        "{%0,%1,%2,%3}, {%4,%5,%6,%7}, {%8,%9}, {%0,%1,%2,%3};"
        : "+f"(c0), "+f"(c1), "+f"(c2), "+f"(c3)
        : "r"(a0), "r"(a1), "r"(a2), "r"(a3), "r"(b0), "r"(b1));
}

__device__ __forceinline__ float silu_f(float u) {
    return u * (1.f / (1.f + __expf(-u)));
}

// ---------------------------------------------------------------------------
// Elementwise tf32 rounding of weights (same layout, streaming)
// ---------------------------------------------------------------------------
template <int WHICH>
__global__ void __launch_bounds__(256) round_tf32_kernel(
    const float* __restrict__ src)
{
    float* dst =
        (WHICH == 0) ? g_wq_r : (WHICH == 1) ? g_wk_r : (WHICH == 2) ? g_wv_r :
        (WHICH == 3) ? g_wo_r : (WHICH == 4) ? g_w1_r : (WHICH == 5) ? g_w3_r :
        g_w2_r;
    size_t i = ((size_t)blockIdx.z * 262144) + (size_t)blockIdx.x * 256 + threadIdx.x;
    float4 v = reinterpret_cast<const float4*>(src)[i];
    float4 o = make_float4(rtf(v.x), rtf(v.y), rtf(v.z), rtf(v.w));
    reinterpret_cast<float4*>(dst)[i] = o;
}

// ---------------------------------------------------------------------------
// RMSNorm. FROM_H=false: x -> g_xn (rounded).
//          FROM_H=true:  g_h -> g_hn (full) + g_hnr (rounded).
// ---------------------------------------------------------------------------
template <bool FROM_H>
__global__ void __launch_bounds__(256) rmsnorm_kernel(
    const float* __restrict__ xin, const float* __restrict__ w)
{
    int t   = blockIdx.x;
    int tid = threadIdx.x;
    const float* src = FROM_H ? g_h : xin;
    const float4* xr = reinterpret_cast<const float4*>(src + (size_t)t * D_);
    float4 v = xr[tid];
    float ss = v.x * v.x + v.y * v.y + v.z * v.z + v.w * v.w;
    #pragma unroll
    for (int o = 16; o > 0; o >>= 1) ss += __shfl_xor_sync(0xffffffffu, ss, o);
    __shared__ float red[8];
    __shared__ float s_inv;
    int warp = tid >> 5, lane = tid & 31;
    if (lane == 0) red[warp] = ss;
    __syncthreads();
    if (tid == 0) {
        float tot = 0.f;
        #pragma unroll
        for (int i = 0; i < 8; i++) tot += red[i];
        s_inv = rsqrtf(tot * (1.0f / (float)D_) + 1e-6f);
    }
    __syncthreads();
    float inv = s_inv;
    const float4* wr = reinterpret_cast<const float4*>(w);
    float4 wv = wr[tid];
    float4 o;
    o.x = v.x * inv * wv.x;
    o.y = v.y * inv * wv.y;
    o.z = v.z * inv * wv.z;
    o.w = v.w * inv * wv.w;
    size_t idx = (size_t)t * D_ + tid * 4;
    float4 orn = make_float4(rtf(o.x), rtf(o.y), rtf(o.z), rtf(o.w));
    if (FROM_H) {
        *reinterpret_cast<float4*>(&g_hn[idx])  = o;
        *reinterpret_cast<float4*>(&g_hnr[idx]) = orn;
    } else {
        *reinterpret_cast<float4*>(&g_xn[idx])  = orn;
    }
}

// ---------------------------------------------------------------------------
// tf32 tensor-core GEMM (R6 register-prefetch structure, ZERO cvt in loop —
// all operands pre-rounded rna). 128x128x32 tile, 256 threads (8 warps),
// warp = 64x32 via 4x4 m16n8k8. K = N = 1024.
// MODE 0: g_xn @ {wq,wk,wv}_r[z] -> g_q/g_k/g_v
// MODE 3: g_attn @ wo_r + R -> g_h
// MODE 4: gather(g_hnr) @ w1_r[e] -> g_t1
// MODE 5: gather(g_hnr) @ w3_r[e], epilogue silu(g_t1)*acc -> g_a (rounded)
// MODE 6: g_a @ w2_r[e] -> g_h2
// ---------------------------------------------------------------------------
template <int MODE>
__global__ void __launch_bounds__(256) mma_gemm_kernel(const float* __restrict__ R)
{
    constexpr int KN = 1024;
    int m0 = blockIdx.y * 128;
    if (MODE >= 4 && m0 >= g_off[E_]) return;

    const float* Bw;
    if (MODE == 0) {
        int z = blockIdx.z;
        Bw = (z == 0) ? g_wq_r : (z == 1) ? g_wk_r : g_wv_r;
    } else if (MODE == 3) {
        Bw = g_wo_r;
    } else {
        int e = 0;
        while (m0 >= g_off[e + 1]) e++;
        const float* base = (MODE == 4) ? g_w1_r : (MODE == 5) ? g_w3_r : g_w2_r;
        Bw = base + (size_t)e * KN * KN;
    }

    int n0 = blockIdx.x * 128;
    int tid = threadIdx.x;

    // A loaders: row lr+32i, k cols lk4..lk4+3
    int lr  = tid >> 3;
    int lk4 = (tid & 7) * 4;
    // B loaders: k row bkr+8i, n cols bn4..bn4+3
    int bkr = tid >> 5;
    int bn4 = (tid & 31) * 4;

    const float* Ap[4];
    bool av[4];
    #pragma unroll
    for (int i = 0; i < 4; i++) {
        int r = m0 + lr + 32 * i;
        if (MODE == 4 || MODE == 5) {
            int tok = g_pair_tok[r];
            av[i] = (tok >= 0);
            Ap[i] = g_hnr + (size_t)(tok < 0 ? 0 : tok) * KN + lk4;
        } else {
            av[i] = true;
            const float* A = (MODE == 3) ? g_attn : (MODE == 6) ? g_a : g_xn;
            Ap[i] = A + (size_t)r * KN + lk4;
        }
    }
    const float* Bp[4];
    #pragma unroll
    for (int i = 0; i < 4; i++)
        Bp[i] = Bw + (size_t)(bkr + 8 * i) * KN + n0 + bn4;

    __shared__ uint32_t Asm[128 * 36];
    __shared__ uint32_t Bsm[32 * 136];

    int lane = tid & 31;
    int wid  = tid >> 5;
    int wr   = wid & 1;
    int wc   = wid >> 1;
    int frow = lane >> 2;
    int kq   = lane & 3;

    float acc[4][4][4] = {};

    float4 a_pre[4], b_pre[4];
    float4 zero = make_float4(0.f, 0.f, 0.f, 0.f);
    #pragma unroll
    for (int i = 0; i < 4; i++) {
        a_pre[i] = av[i] ? *(const float4*)Ap[i] : zero;
        b_pre[i] = *(const float4*)Bp[i];
    }

    for (int kb = 0; kb < KN; kb += 32) {
        __syncthreads();
        #pragma unroll
        for (int i = 0; i < 4; i++) {
            *(uint4*)&Asm[(lr + 32 * i) * 36 + lk4] =
                *reinterpret_cast<uint4*>(&a_pre[i]);      // raw bits (pre-rounded)
            *(uint4*)&Bsm[(bkr + 8 * i) * 136 + bn4] =
                *reinterpret_cast<uint4*>(&b_pre[i]);
        }
        __syncthreads();
        if (kb + 32 < KN) {
            #pragma unroll
            for (int i = 0; i < 4; i++) {
                a_pre[i] = av[i] ? *(const float4*)(Ap[i] + kb + 32) : zero;
                b_pre[i] = *(const float4*)(Bp[i] + (size_t)(kb + 32) * KN);
            }
        }
        #pragma unroll
        for (int ks = 0; ks < 32; ks += 8) {
            uint32_t af[4][4];
            #pragma unroll
            for (int mt = 0; mt < 4; mt++) {
                int m = wr * 64 + mt * 16 + frow;
                af[mt][0] = Asm[m * 36 + ks + kq];
                af[mt][1] = Asm[(m + 8) * 36 + ks + kq];
                af[mt][2] = Asm[m * 36 + ks + kq + 4];
                af[mt][3] = Asm[(m + 8) * 36 + ks + kq + 4];
            }
            uint32_t bf[4][2];
            #pragma unroll
            for (int nt = 0; nt < 4; nt++) {
                int n = wc * 32 + nt * 8 + frow;
                bf[nt][0] = Bsm[(ks + kq) * 136 + n];
                bf[nt][1] = Bsm[(ks + kq + 4) * 136 + n];
            }
            #pragma unroll
            for (int mt = 0; mt < 4; mt++)
                #pragma unroll
                for (int nt = 0; nt < 4; nt++)
                    mma_tf32(acc[mt][nt][0], acc[mt][nt][1],
                             acc[mt][nt][2], acc[mt][nt][3],
                             af[mt][0], af[mt][1], af[mt][2], af[mt][3],
                             bf[nt][0], bf[nt][1]);
        }
    }

    #pragma unroll
    for (int mt = 0; mt < 4; mt++) {
        int r = m0 + wr * 64 + mt * 16 + frow;
        #pragma unroll
        for (int nt = 0; nt < 4; nt++) {
            int c = n0 + wc * 32 + nt * 8 + kq * 2;
            size_t i0 = (size_t)r * KN + c;
            size_t i1 = (size_t)(r + 8) * KN + c;
            float2 v0 = make_float2(acc[mt][nt][0], acc[mt][nt][1]);
            float2 v1 = make_float2(acc[mt][nt][2], acc[mt][nt][3]);
            if (MODE == 3) {
                float2 r0 = *(const float2*)(R + i0);
                float2 r1 = *(const float2*)(R + i1);
                v0.x += r0.x; v0.y += r0.y;
                v1.x += r1.x; v1.y += r1.y;
            }
            if (MODE == 5) {
                float2 t10 = *(const float2*)(g_t1 + i0);
                float2 t11 = *(const float2*)(g_t1 + i1);
                v0.x = rtf(v0.x * silu_f(t10.x));
                v0.y = rtf(v0.y * silu_f(t10.y));
                v1.x = rtf(v1.x * silu_f(t11.x));
                v1.y = rtf(v1.y * silu_f(t11.y));
            }
            float* C;
            if (MODE == 0) {
                int z = blockIdx.z;
                C = (z == 0) ? g_q : (z == 1) ? g_k : g_v;
            } else {
                C = (MODE == 3) ? g_h : (MODE == 4) ? g_t1 :
                    (MODE == 5) ? g_a : g_h2;
            }
            *(float2*)(C + i0) = v0;
            *(float2*)(C + i1) = v1;
        }
    }
}

// ---------------------------------------------------------------------------
// Tensor-core flash attention (tf32), causal; epilogue writes rounded g_attn.
// ---------------------------------------------------------------------------
__global__ void __launch_bounds__(128) flash_mma_kernel()
{
    __shared__ uint32_t KVs[64 * 68];
    __shared__ uint32_t Ps[64 * 68];

    int qt = (int)gridDim.x - 1 - (int)blockIdx.x;
    int h = blockIdx.y, b = blockIdx.z;
    int q0 = qt * 64;
    int tid = threadIdx.x;
    int w = tid >> 5, lane = tid & 31;
    int frow = lane >> 2, kq = lane & 3;
    int qw = w * 16;
    size_t base = ((size_t)b * S_) * D_ + (size_t)h * HD_;
    const float NI = -3.0e38f;

    uint32_t qf[8][4];
    {
        const float* Q0 = g_q + base + (size_t)(q0 + qw + frow) * D_;
        const float* Q1 = g_q + base + (size_t)(q0 + qw + frow + 8) * D_;
        #pragma unroll
        for (int ks = 0; ks < 8; ks++) {
            qf[ks][0] = f2tf32(0.125f * Q0[ks * 8 + kq]);
            qf[ks][1] = f2tf32(0.125f * Q1[ks * 8 + kq]);
            qf[ks][2] = f2tf32(0.125f * Q0[ks * 8 + kq + 4]);
            qf[ks][3] = f2tf32(0.125f * Q1[ks * 8 + kq + 4]);
        }
    }

    float oacc[8][4] = {};
    float m0 = NI, m1 = NI, l0 = 0.f, l1 = 0.f;

    for (int kt = 0; kt <= qt; kt++) {
        int k0 = kt * 64;
        __syncthreads();
        for (int i = tid; i < 1024; i += 128) {
            int r = i >> 4, c4 = (i & 15) * 4;
            float4 v = *(const float4*)&g_k[base + (size_t)(k0 + r) * D_ + c4];
            KVs[r * 68 + c4 + 0] = f2tf32(v.x);
            KVs[r * 68 + c4 + 1] = f2tf32(v.y);
            KVs[r * 68 + c4 + 2] = f2tf32(v.z);
            KVs[r * 68 + c4 + 3] = f2tf32(v.w);
        }
        __syncthreads();

        float sacc[8][4] = {};
        #pragma unroll
        for (int ks = 0; ks < 8; ks++) {
            uint32_t bf[8][2];
            #pragma unroll
            for (int nt = 0; nt < 8; nt++) {
                bf[nt][0] = KVs[(nt * 8 + frow) * 68 + ks * 8 + kq];
                bf[nt][1] = KVs[(nt * 8 + frow) * 68 + ks * 8 + kq + 4];
            }
            #pragma unroll
            for (int nt = 0; nt < 8; nt++)
                mma_tf32(sacc[nt][0], sacc[nt][1], sacc[nt][2], sacc[nt][3],
                         qf[ks][0], qf[ks][1], qf[ks][2], qf[ks][3],
                         bf[nt][0], bf[nt][1]);
        }

        if (kt == qt) {
            int r0g = qw + frow;
            #pragma unroll
            for (int nt = 0; nt < 8; nt++) {
                int c0g = nt * 8 + 2 * kq;
                if (c0g     > r0g)     sacc[nt][0] = NI;
                if (c0g + 1 > r0g)     sacc[nt][1] = NI;
                if (c0g     > r0g + 8) sacc[nt][2] = NI;
                if (c0g + 1 > r0g + 8) sacc[nt][3] = NI;
            }
        }

        float tm0 = NI, tm1 = NI;
        #pragma unroll
        for (int nt = 0; nt < 8; nt++) {
            tm0 = fmaxf(tm0, fmaxf(sacc[nt][0], sacc[nt][1]));
            tm1 = fmaxf(tm1, fmaxf(sacc[nt][2], sacc[nt][3]));
        }
        tm0 = fmaxf(tm0, __shfl_xor_sync(0xffffffffu, tm0, 1));
        tm0 = fmaxf(tm0, __shfl_xor_sync(0xffffffffu, tm0, 2));
        tm1 = fmaxf(tm1, __shfl_xor_sync(0xffffffffu, tm1, 1));
        tm1 = fmaxf(tm1, __shfl_xor_sync(0xffffffffu, tm1, 2));
        float mn0 = fmaxf(m0, tm0), mn1 = fmaxf(m1, tm1);
        float rs0 = 0.f, rs1 = 0.f;
        uint32_t* Pw = &Ps[(qw + frow) * 68];
        uint32_t* Pw8 = &Ps[(qw + frow + 8) * 68];
        #pragma unroll
        for (int nt = 0; nt < 8; nt++) {
            float p00 = __expf(sacc[nt][0] - mn0);
            float p01 = __expf(sacc[nt][1] - mn0);
            float p10 = __expf(sacc[nt][2] - mn1);
            float p11 = __expf(sacc[nt][3] - mn1);
            rs0 += p00 + p01;
            rs1 += p10 + p11;
            int c = nt * 8 + 2 * kq;
            Pw[c]      = f2tf32(p00);
            Pw[c + 1]  = f2tf32(p01);
            Pw8[c]     = f2tf32(p10);
            Pw8[c + 1] = f2tf32(p11);
        }
        rs0 += __shfl_xor_sync(0xffffffffu, rs0, 1);
        rs0 += __shfl_xor_sync(0xffffffffu, rs0, 2);
        rs1 += __shfl_xor_sync(0xffffffffu, rs1, 1);
        rs1 += __shfl_xor_sync(0xffffffffu, rs1, 2);
        float al0 = __expf(m0 - mn0), al1 = __expf(m1 - mn1);
        l0 = l0 * al0 + rs0;
        l1 = l1 * al1 + rs1;
        m0 = mn0; m1 = mn1;
        #pragma unroll
        for (int nt = 0; nt < 8; nt++) {
            oacc[nt][0] *= al0; oacc[nt][1] *= al0;
            oacc[nt][2] *= al1; oacc[nt][3] *= al1;
        }
        __syncwarp();
        __syncthreads();

        for (int i = tid; i < 1024; i += 128) {
            int r = i >> 4, c4 = (i & 15) * 4;
            float4 v = *(const float4*)&g_v[base + (size_t)(k0 + r) * D_ + c4];
            KVs[r * 68 + c4 + 0] = f2tf32(v.x);
            KVs[r * 68 + c4 + 1] = f2tf32(v.y);
            KVs[r * 68 + c4 + 2] = f2tf32(v.z);
            KVs[r * 68 + c4 + 3] = f2tf32(v.w);
        }
        __syncthreads();

        #pragma unroll
        for (int ks = 0; ks < 8; ks++) {
            uint32_t af[4];
            af[0] = Ps[(qw + frow) * 68 + ks * 8 + kq];
            af[1] = Ps[(qw + frow + 8) * 68 + ks * 8 + kq];
            af[2] = Ps[(qw + frow) * 68 + ks * 8 + kq + 4];
            af[3] = Ps[(qw + frow + 8) * 68 + ks * 8 + kq + 4];
            #pragma unroll
            for (int nt = 0; nt < 8; nt++) {
                uint32_t b0 = KVs[(ks * 8 + kq) * 68 + nt * 8 + frow];
                uint32_t b1 = KVs[(ks * 8 + kq + 4) * 68 + nt * 8 + frow];
                mma_tf32(oacc[nt][0], oacc[nt][1], oacc[nt][2], oacc[nt][3],
                         af[0], af[1], af[2], af[3], b0, b1);
            }
        }
    }

    float inv0 = 1.f / l0, inv1 = 1.f / l1;
    float* O0 = g_attn + base + (size_t)(q0 + qw + frow) * D_;
    float* O1 = g_attn + base + (size_t)(q0 + qw + frow + 8) * D_;
    #pragma unroll
    for (int nt = 0; nt < 8; nt++) {
        int c = nt * 8 + 2 * kq;
        *(float2*)(O0 + c) = make_float2(rtf(oacc[nt][0] * inv0),
                                         rtf(oacc[nt][1] * inv0));
        *(float2*)(O1 + c) = make_float2(rtf(oacc[nt][2] * inv1),
                                         rtf(oacc[nt][3] * inv1));
    }
}

// ---------------------------------------------------------------------------
// Router / dispatch (full-fp32 g_hn)
// ---------------------------------------------------------------------------
__global__ void __launch_bounds__(256) router_kernel(const float* __restrict__ rw)
{
    int t = (blockIdx.x * blockDim.x + threadIdx.x) >> 5;
    int lane = threadIdx.x & 31;
    if (t >= T_) return;
    float acc[8] = {0, 0, 0, 0, 0, 0, 0, 0};
    const float* xr = g_hn + (size_t)t * D_;
    for (int d = lane * 4; d < D_; d += 128) {
        float4 xv = *reinterpret_cast<const float4*>(xr + d);
        float xs[4] = {xv.x, xv.y, xv.z, xv.w};
        #pragma unroll
        for (int c = 0; c < 4; c++) {
            const float4* rp = reinterpret_cast<const float4*>(rw + (size_t)(d + c) * E_);
            float4 ra = rp[0], rb = rp[1];
            acc[0] += xs[c] * ra.x; acc[1] += xs[c] * ra.y;
            acc[2] += xs[c] * ra.z; acc[3] += xs[c] * ra.w;
            acc[4] += xs[c] * rb.x; acc[5] += xs[c] * rb.y;
            acc[6] += xs[c] * rb.z; acc[7] += xs[c] * rb.w;
        }
    }
    #pragma unroll
    for (int e = 0; e < 8; e++)
        #pragma unroll
        for (int o = 16; o > 0; o >>= 1)
            acc[e] += __shfl_xor_sync(0xffffffffu, acc[e], o);
    if (lane == 0) {
        int e0 = 0; float b0 = acc[0];
        #pragma unroll
        for (int e = 1; e < 8; e++) if (acc[e] > b0) { b0 = acc[e]; e0 = e; }
        int e1 = -1; float b1 = -3.4e38f;
        #pragma unroll
        for (int e = 0; e < 8; e++)
            if (e != e0 && acc[e] > b1) { b1 = acc[e]; e1 = e; }
        float ex = __expf(b1 - b0);
        float inv = 1.0f / (1.0f + ex);
        g_topk_idx[t * 2 + 0] = e0;
        g_topk_idx[t * 2 + 1] = e1;
        g_topk_gate[t * 2 + 0] = inv;
        g_topk_gate[t * 2 + 1] = ex * inv;
        atomicAdd(&g_cnt[e0], 1);
        atomicAdd(&g_cnt[e1], 1);
    }
}

__global__ void init_kernel()
{
    int i = blockIdx.x * blockDim.x + threadIdx.x;
    if (i < PMAX_) g_pair_tok[i] = -1;
    if (i < E_) g_cnt[i] = 0;
}

__global__ void offsets_kernel()
{
    int off = 0;
    for (int e = 0; e < E_; e++) {
        g_off[e] = off;
        off += (g_cnt[e] + 127) & ~127;
        g_cur[e] = 0;
    }
    g_off[E_] = off;
}

__global__ void __launch_bounds__(256) scatter_kernel()
{
    int t = blockIdx.x * blockDim.x + threadIdx.x;
    if (t >= T_) return;
    #pragma unroll
    for (int k = 0; k < 2; k++) {
        int e = g_topk_idx[t * 2 + k];
        int pos = g_off[e] + atomicAdd(&g_cur[e], 1);
        g_pair_tok[pos] = t;
        g_tok_pos[t * 2 + k] = pos;
    }
}

// ---------------------------------------------------------------------------
// Combine
// ---------------------------------------------------------------------------
__global__ void __launch_bounds__(256) combine_kernel(float* __restrict__ out)
{
    int i = blockIdx.x * blockDim.x + threadIdx.x;
    int t = i >> 8;
    int d = (i & 255) * 4;
    int p0 = g_tok_pos[t * 2 + 0], p1 = g_tok_pos[t * 2 + 1];
    float g0 = g_topk_gate[t * 2 + 0], g1 = g_topk_gate[t * 2 + 1];
    float4 hv = *reinterpret_cast<const float4*>(&g_h[(size_t)t * D_ + d]);
    float4 a = *reinterpret_cast<const float4*>(&g_h2[(size_t)p0 * D_ + d]);
    float4 b = *reinterpret_cast<const float4*>(&g_h2[(size_t)p1 * D_ + d]);
    float4 o;
    o.x = hv.x + g0 * a.x + g1 * b.x;
    o.y = hv.y + g0 * a.y + g1 * b.y;
    o.z = hv.z + g0 * a.z + g1 * b.z;
    o.w = hv.w + g0 * a.w + g1 * b.w;
    *reinterpret_cast<float4*>(&out[(size_t)i * 4]) = o;
}

// ---------------------------------------------------------------------------
// Launch: kernel launches ONLY
// ---------------------------------------------------------------------------
extern "C" void kernel_launch(void* const* d_in, const int* in_sizes, int n_in,
                              void* d_out, int out_size)
{
    const float* x   = (const float*)d_in[0];
    const float* anw = (const float*)d_in[1];
    const float* wq  = (const float*)d_in[2];
    const float* wk  = (const float*)d_in[3];
    const float* wv  = (const float*)d_in[4];
    const float* wo  = (const float*)d_in[5];
    const float* fnw = (const float*)d_in[6];
    const float* rw  = (const float*)d_in[7];
    const float* w1  = (const float*)d_in[8];
    const float* w3  = (const float*)d_in[9];
    const float* w2  = (const float*)d_in[10];
    float* out = (float*)d_out;

    dim3 gr1(1024, 1, 1), gr8(1024, 1, 8);
    round_tf32_kernel<0><<<gr1, 256>>>(wq);
    round_tf32_kernel<1><<<gr1, 256>>>(wk);
    round_tf32_kernel<2><<<gr1, 256>>>(wv);
    round_tf32_kernel<3><<<gr1, 256>>>(wo);
    round_tf32_kernel<4><<<gr8, 256>>>(w1);
    round_tf32_kernel<5><<<gr8, 256>>>(w3);
    round_tf32_kernel<6><<<gr8, 256>>>(w2);

    dim3 gqkv(8, 32, 3);
    dim3 gproj(8, 32);
    dim3 gmoe(8, PMAX_ / 128);

    rmsnorm_kernel<false><<<T_, 256>>>(x, anw);
    mma_gemm_kernel<0><<<gqkv, 256>>>(nullptr);
    flash_mma_kernel<<<dim3(S_ / 64, H_, B_), 128>>>();
    mma_gemm_kernel<3><<<gproj, 256>>>(x);
    rmsnorm_kernel<true><<<T_, 256>>>(nullptr, fnw);

    init_kernel<<<(PMAX_ + 255) / 256, 256>>>();
    router_kernel<<<T_ / 8, 256>>>(rw);
    offsets_kernel<<<1, 1>>>();
    scatter_kernel<<<T_ / 256, 256>>>();
    mma_gemm_kernel<4><<<gmoe, 256>>>(nullptr);
    mma_gemm_kernel<5><<<gmoe, 256>>>(nullptr);
    mma_gemm_kernel<6><<<gmoe, 256>>>(nullptr);
    combine_kernel<<<(T_ * D_ / 4) / 256, 256>>>(out);
}